// round 17
// baseline (speedup 1.0000x reference)
#include <cuda_runtime.h>
#include <cstdint>

// Problem constants (fixed by the dataset)
#define BB    4
#define NBC   128
#define NINT  4096
#define HID   64

// ---------------------------------------------------------------------------
// Device scratch (allocation-free)
// ---------------------------------------------------------------------------
__device__ float g_avec[BB * NBC * HID];              // a[b][nbc][k]

// ---------------------------------------------------------------------------
// fp16 helpers (plain sm_80+)
// ---------------------------------------------------------------------------
__device__ __forceinline__ uint32_t pack_f16x2(float lo, float hi) {
    uint32_t r;
    asm("cvt.rn.f16x2.f32 %0, %1, %2;" : "=r"(r) : "f"(hi), "f"(lo));
    return r;
}
__device__ __forceinline__ uint32_t add_f16x2(uint32_t a, uint32_t b) {
    uint32_t r;
    asm("add.f16x2 %0, %1, %2;" : "=r"(r) : "r"(a), "r"(b));
    return r;
}
__device__ __forceinline__ uint32_t relu_f16x2(uint32_t a) {
    uint32_t r;
    asm("max.f16x2 %0, %1, %2;" : "=r"(r) : "r"(a), "r"(0u));
    return r;
}
// f16-accum MMA, C given explicitly
__device__ __forceinline__ void mma_f16_init(uint32_t& d0, uint32_t& d1,
                                             uint32_t a0, uint32_t a1, uint32_t a2, uint32_t a3,
                                             uint32_t b0, uint32_t b1, uint32_t c) {
    asm volatile("mma.sync.aligned.m16n8k16.row.col.f16.f16.f16.f16 "
                 "{%0,%1}, {%2,%3,%4,%5}, {%6,%7}, {%8,%8};"
                 : "=r"(d0), "=r"(d1)
                 : "r"(a0), "r"(a1), "r"(a2), "r"(a3), "r"(b0), "r"(b1), "r"(c));
}
__device__ __forceinline__ void mma_f16_acc(uint32_t& d0, uint32_t& d1,
                                            uint32_t a0, uint32_t a1, uint32_t a2, uint32_t a3,
                                            uint32_t b0, uint32_t b1) {
    asm volatile("mma.sync.aligned.m16n8k16.row.col.f16.f16.f16.f16 "
                 "{%0,%1}, {%2,%3,%4,%5}, {%6,%7}, {%0,%1};"
                 : "+r"(d0), "+r"(d1)
                 : "r"(a0), "r"(a1), "r"(a2), "r"(a3), "r"(b0), "r"(b1));
}
// f32-accum epilogue MMA (f16 inputs)
__device__ __forceinline__ void mma_f16_f32(float& d0, float& d1, float& d2, float& d3,
                                            uint32_t a0, uint32_t a1, uint32_t a2, uint32_t a3,
                                            uint32_t b0, uint32_t b1) {
    asm volatile("mma.sync.aligned.m16n8k16.row.col.f32.f16.f16.f32 "
                 "{%0,%1,%2,%3}, {%4,%5,%6,%7}, {%8,%9}, {%0,%1,%2,%3};"
                 : "+f"(d0), "+f"(d1), "+f"(d2), "+f"(d3)
                 : "r"(a0), "r"(a1), "r"(a2), "r"(a3), "r"(b0), "r"(b1));
}

__device__ __forceinline__ uint32_t smem_u32(const void* p) {
    uint32_t a;
    asm("{ .reg .u64 t; cvta.to.shared.u64 t, %1; cvt.u32.u64 %0, t; }" : "=r"(a) : "l"(p));
    return a;
}
__device__ __forceinline__ void cp_async16(uint32_t saddr, const void* g) {
    asm volatile("cp.async.cg.shared.global [%0], [%1], 16;" :: "r"(saddr), "l"(g));
}

// ---------------------------------------------------------------------------
// prepA kernel: per (b,nbc): bf = relu(relu(binfo@W0+b0)@W1+b1); a = bf@G0w[:64]
// Also initializes d_out to G2b[0].
// ---------------------------------------------------------------------------
__global__ void __launch_bounds__(128)
prepA_kernel(const float* __restrict__ binfo,
             const float* __restrict__ W0, const float* __restrict__ b0,
             const float* __restrict__ W1, const float* __restrict__ b1,
             const float* __restrict__ G0w,
             const float* __restrict__ G2b,
             float* __restrict__ out) {
    __shared__ __align__(16) float sW1[HID * HID];
    __shared__ __align__(16) float sG0[HID * HID];
    __shared__ float sbf0[2][HID];
    __shared__ float sbf1[2][HID];

    const int tid = threadIdx.x;
    const int sub = tid >> 6;       // 0..1
    const int j   = tid & 63;
    const int bn  = blockIdx.x * 2 + sub;    // 0..511

    {   // async prefetch of big weights (overlaps with stage 0)
        uint32_t sw = smem_u32(sW1);
        uint32_t sg = smem_u32(sG0);
        #pragma unroll
        for (int i = tid; i < 1024; i += 128) cp_async16(sw + i * 16, W1 + i * 4);
        #pragma unroll
        for (int i = tid; i < 1024; i += 128) cp_async16(sg + i * 16, G0w + i * 4);
        asm volatile("cp.async.commit_group;" ::: "memory");
    }

    if (tid < 64) out[blockIdx.x * 64 + tid] = G2b[0];

    const float* bi = binfo + bn * 3;
    float x0 = bi[0], x1 = bi[1], x2 = bi[2];
    sbf0[sub][j] = fmaxf(
        fmaf(x0, W0[j], fmaf(x1, W0[64 + j], fmaf(x2, W0[128 + j], b0[j]))), 0.0f);

    asm volatile("cp.async.wait_group 0;" ::: "memory");
    __syncthreads();

    float s = b1[j];
    #pragma unroll 16
    for (int k = 0; k < HID; k++) s = fmaf(sbf0[sub][k], sW1[k * 64 + j], s);
    sbf1[sub][j] = fmaxf(s, 0.0f);
    __syncthreads();

    float a = 0.0f;
    #pragma unroll 16
    for (int k = 0; k < HID; k++) a = fmaf(sbf1[sub][k], sG0[k * 64 + j], a);
    g_avec[bn * 64 + j] = a;
}

// ---------------------------------------------------------------------------
// Main kernel: fp16 m16n8k16, balanced 296-CTA partition, vectorized fetches,
// SPLIT accumulation chains: per (kc, chain) two 2-deep f16 HMMA halves
// (C=bias / C=0) combined with one add.f16x2 — doubles independent chains and
// halves serial HMMA depth. B fragments all from smem (registers freed so the
// scheduler can overlap kc blocks).
// ---------------------------------------------------------------------------
#define SMEM_AP_BYTES 16384
#define SMEM_W_BYTES  8192
#define SMEM_WX_OFF   (SMEM_AP_BYTES + SMEM_W_BYTES)
#define SMEM_TOTAL    (SMEM_WX_OFF + 3 * 64 * 4)

__global__ void __launch_bounds__(256, 2)
main_kernel(const float* __restrict__ G1w,
            const float* __restrict__ G1b,
            const float* __restrict__ G2w,
            const float* __restrict__ coords,
            const float* __restrict__ G0w,
            const float* __restrict__ G0b,
            float* __restrict__ out) {
    extern __shared__ char smem[];
    uint4* s_ap4 = reinterpret_cast<uint4*>(smem);
    uint4* s_w4  = reinterpret_cast<uint4*>(smem + SMEM_AP_BYTES);
    float* s_wx  = reinterpret_cast<float*>(smem + SMEM_WX_OFF);
    float* s_wy  = s_wx + 64;
    float* s_gb  = s_wy + 64;

    const int tid  = threadIdx.x;
    const int wid  = tid >> 5;
    const int lane = tid & 31;
    const int gid  = lane >> 2;    // 0..7
    const int tig  = lane & 3;     // 0..3

    // contiguous unit range for this CTA (4096 units over 296 CTAs)
    const int u0 = (int)(((long long)blockIdx.x * 512) / 37);
    const int u1 = (int)(((long long)(blockIdx.x + 1) * 512) / 37);

    // --- one-time prologue: stage weights (vector-packed) ---
    {   // s_w4[nb*64 + sel*32 + ln] = two adjacent s-fragments
        #pragma unroll
        for (int idx = tid; idx < 8 * 2 * 32; idx += 256) {   // 512
            int nb   = idx >> 6;
            int rest = idx & 63;
            int sel  = rest >> 5;
            int ln   = rest & 31;
            int tg   = ln & 3;
            int gd   = ln >> 2;
            int col  = nb * 8 + gd;
            int ka   = 16 * (2 * sel)     + 2 * tg;
            int kb   = 16 * (2 * sel + 1) + 2 * tg;
            uint4 v;
            v.x = pack_f16x2(G1w[ka * 64 + col],       G1w[(ka + 1) * 64 + col]);
            v.y = pack_f16x2(G1w[(ka + 8) * 64 + col], G1w[(ka + 9) * 64 + col]);
            v.z = pack_f16x2(G1w[kb * 64 + col],       G1w[(kb + 1) * 64 + col]);
            v.w = pack_f16x2(G1w[(kb + 8) * 64 + col], G1w[(kb + 9) * 64 + col]);
            s_w4[nb * 64 + sel * 32 + ln] = v;
        }
    }
    if (tid < 64) {
        s_wx[tid] = G0w[64 * 64 + tid];
        s_wy[tid] = G0w[65 * 64 + tid];
        s_gb[tid] = G0b[tid];
    }
    __syncthreads();

    // loop-invariant: bias C-operands and epilogue B fragments
    uint32_t bb[8];
    #pragma unroll
    for (int nb = 0; nb < 8; nb++) {
        float2 g = *reinterpret_cast<const float2*>(G1b + nb * 8 + 2 * tig);
        bb[nb] = pack_f16x2(g.x, g.y);
    }
    uint2 b2[4];
    #pragma unroll
    for (int kc = 0; kc < 4; kc++) {
        int k = 16 * kc + 2 * tig;
        float2 glo = *reinterpret_cast<const float2*>(G2w + k);
        float2 ghi = *reinterpret_cast<const float2*>(G2w + k + 8);
        b2[kc] = make_uint2(pack_f16x2(glo.x, glo.y), pack_f16x2(ghi.x, ghi.y));
    }

    const float scale = 1.0f / (float)NBC;
    int cur_b = -1;

    int u = u0;
    while (u < u1) {
        const int b    = u >> 10;
        const int tile = (u >> 5) & 31;
        int segEnd = ((u >> 5) + 1) << 5;
        if (segEnd > u1) segEnd = u1;

        if (b != cur_b) {
            __syncthreads();
            const float* abase = g_avec + (size_t)b * NBC * HID;
            #pragma unroll
            for (int idx = tid; idx < NBC * 8; idx += 256) {   // 1024
                int nn   = idx >> 3;
                int rest = idx & 7;
                int tg   = rest >> 1;
                int half = rest & 1;
                const float* r0 = abase + nn * 64 + 16 * (2 * half)     + 2 * tg;
                const float* r1 = abase + nn * 64 + 16 * (2 * half + 1) + 2 * tg;
                float2 l0 = *reinterpret_cast<const float2*>(r0);
                float2 h0 = *reinterpret_cast<const float2*>(r0 + 8);
                float2 l1 = *reinterpret_cast<const float2*>(r1);
                float2 h1 = *reinterpret_cast<const float2*>(r1 + 8);
                uint4 v;
                v.x = pack_f16x2(l0.x, l0.y);
                v.y = pack_f16x2(h0.x, h0.y);
                v.z = pack_f16x2(l1.x, l1.y);
                v.w = pack_f16x2(h1.x, h1.y);
                s_ap4[idx] = v;
            }
            __syncthreads();
            cur_b = b;
        }

        // rebuild c fragments for this (b, tile)
        const int rowl = tile * 128 + wid * 16 + gid;
        const int row0 = b * NINT + rowl;
        uint32_t cp0[8], cp1[8];
        {
            float cx0 = coords[(size_t)row0 * 2 + 0];
            float cy0 = coords[(size_t)row0 * 2 + 1];
            float cx1 = coords[(size_t)(row0 + 8) * 2 + 0];
            float cy1 = coords[(size_t)(row0 + 8) * 2 + 1];
            #pragma unroll
            for (int s = 0; s < 4; s++) {
                #pragma unroll
                for (int h = 0; h < 2; h++) {
                    int k = 16 * s + 2 * tig + 8 * h;
                    float wxa = s_wx[k],     wya = s_wy[k],     gba = s_gb[k];
                    float wxb = s_wx[k + 1], wyb = s_wy[k + 1], gbb = s_gb[k + 1];
                    cp0[2 * s + h] = pack_f16x2(fmaf(cx0, wxa, fmaf(cy0, wya, gba)),
                                                fmaf(cx0, wxb, fmaf(cy0, wyb, gbb)));
                    cp1[2 * s + h] = pack_f16x2(fmaf(cx1, wxa, fmaf(cy1, wya, gba)),
                                                fmaf(cx1, wxb, fmaf(cy1, wyb, gbb)));
                }
            }
        }

        const int nn0 = (u & 31) * 4;
        const int nn1 = nn0 + (segEnd - u) * 4;

        float Da0 = 0.0f, Da1 = 0.0f, Da2 = 0.0f, Da3 = 0.0f;
        float Db0 = 0.0f, Db1 = 0.0f, Db2 = 0.0f, Db3 = 0.0f;

        #pragma unroll 1
        for (int nn = nn0; nn < nn1; nn++) {
            // A operands: 2 x LDS.128 (4-address broadcast)
            uint4 apA = s_ap4[nn * 8 + tig * 2 + 0];
            uint4 apB = s_ap4[nn * 8 + tig * 2 + 1];

            // A fragments: h1 = relu(a + c), f16x2
            uint32_t A0[4], A1[4], A2v[4], A3[4];
            A0[0]  = relu_f16x2(add_f16x2(apA.x, cp0[0]));
            A1[0]  = relu_f16x2(add_f16x2(apA.x, cp1[0]));
            A2v[0] = relu_f16x2(add_f16x2(apA.y, cp0[1]));
            A3[0]  = relu_f16x2(add_f16x2(apA.y, cp1[1]));
            A0[1]  = relu_f16x2(add_f16x2(apA.z, cp0[2]));
            A1[1]  = relu_f16x2(add_f16x2(apA.z, cp1[2]));
            A2v[1] = relu_f16x2(add_f16x2(apA.w, cp0[3]));
            A3[1]  = relu_f16x2(add_f16x2(apA.w, cp1[3]));
            A0[2]  = relu_f16x2(add_f16x2(apB.x, cp0[4]));
            A1[2]  = relu_f16x2(add_f16x2(apB.x, cp1[4]));
            A2v[2] = relu_f16x2(add_f16x2(apB.y, cp0[5]));
            A3[2]  = relu_f16x2(add_f16x2(apB.y, cp1[5]));
            A0[3]  = relu_f16x2(add_f16x2(apB.z, cp0[6]));
            A1[3]  = relu_f16x2(add_f16x2(apB.z, cp1[6]));
            A2v[3] = relu_f16x2(add_f16x2(apB.w, cp0[7]));
            A3[3]  = relu_f16x2(add_f16x2(apB.w, cp1[7]));

            #pragma unroll
            for (int kc = 0; kc < 4; kc++) {
                const int nb0 = 2 * kc, nb1 = 2 * kc + 1;
                // Split chains: (s0,s1) with C=bias || (s2,s3) with C=0; combine.
                uint32_t dA0, dA1, dB0, dB1, fA0, fA1, fB0, fB1;
                {
                    uint4 q0 = s_w4[nb0 * 64 + lane];
                    uint4 q1 = s_w4[nb0 * 64 + 32 + lane];
                    mma_f16_init(dA0, dA1, A0[0], A1[0], A2v[0], A3[0], q0.x, q0.y, bb[nb0]);
                    mma_f16_acc (dA0, dA1, A0[1], A1[1], A2v[1], A3[1], q0.z, q0.w);
                    mma_f16_init(dB0, dB1, A0[2], A1[2], A2v[2], A3[2], q1.x, q1.y, 0u);
                    mma_f16_acc (dB0, dB1, A0[3], A1[3], A2v[3], A3[3], q1.z, q1.w);
                }
                {
                    uint4 q0 = s_w4[nb1 * 64 + lane];
                    uint4 q1 = s_w4[nb1 * 64 + 32 + lane];
                    mma_f16_init(fA0, fA1, A0[0], A1[0], A2v[0], A3[0], q0.x, q0.y, bb[nb1]);
                    mma_f16_acc (fA0, fA1, A0[1], A1[1], A2v[1], A3[1], q0.z, q0.w);
                    mma_f16_init(fB0, fB1, A0[2], A1[2], A2v[2], A3[2], q1.x, q1.y, 0u);
                    mma_f16_acc (fB0, fB1, A0[3], A1[3], A2v[3], A3[3], q1.z, q1.w);
                }
                // combine halves + relu -> epilogue A fragments
                uint32_t d0 = relu_f16x2(add_f16x2(dA0, dB0));
                uint32_t d1 = relu_f16x2(add_f16x2(dA1, dB1));
                uint32_t f0 = relu_f16x2(add_f16x2(fA0, fB0));
                uint32_t f1 = relu_f16x2(add_f16x2(fA1, fB1));
                if (kc & 1)
                    mma_f16_f32(Db0, Db1, Db2, Db3, d0, d1, f0, f1, b2[kc].x, b2[kc].y);
                else
                    mma_f16_f32(Da0, Da1, Da2, Da3, d0, d1, f0, f1, b2[kc].x, b2[kc].y);
            }
        }

        // flush this segment's partial sums (D2 n-cols identical -> no reduce)
        if (tig == 0) {
            atomicAdd(out + row0,     (Da0 + Db0) * scale);
            atomicAdd(out + row0 + 8, (Da2 + Db2) * scale);
        }

        u = segEnd;
    }
}

// ---------------------------------------------------------------------------
// Launch.  Inputs (metadata order):
// 0 boundary_info 1 interior_coords 2 W0 3 b0 4 W1 5 b1
// 6 G0w 7 G0b 8 G1w 9 G1b 10 G2w 11 G2b 12 interior_h 13 interior_w
// ---------------------------------------------------------------------------
extern "C" void kernel_launch(void* const* d_in, const int* in_sizes, int n_in,
                              void* d_out, int out_size) {
    const float* binfo  = (const float*)d_in[0];
    const float* coords = (const float*)d_in[1];
    const float* W0     = (const float*)d_in[2];
    const float* b0     = (const float*)d_in[3];
    const float* W1     = (const float*)d_in[4];
    const float* b1     = (const float*)d_in[5];
    const float* G0w    = (const float*)d_in[6];
    const float* G0b    = (const float*)d_in[7];
    const float* G1w    = (const float*)d_in[8];
    const float* G1b    = (const float*)d_in[9];
    const float* G2w    = (const float*)d_in[10];
    const float* G2b    = (const float*)d_in[11];
    float* out          = (float*)d_out;

    cudaFuncSetAttribute(main_kernel, cudaFuncAttributeMaxDynamicSharedMemorySize, SMEM_TOTAL);

    prepA_kernel<<<256, 128>>>(binfo, W0, b0, W1, b1, G0w, G2b, out);
    main_kernel<<<296, 256, SMEM_TOTAL>>>(G1w, G1b, G2w, coords, G0w, G0b, out);
}